// round 15
// baseline (speedup 1.0000x reference)
#include <cuda_runtime.h>
#include <cuda_fp16.h>
#include <stdint.h>

#define N_TOK 16384
#define D_DIM 2048
#define H_DIM 1024
#define N_EXP 16

// ------------------------- scratch (device globals; no allocs) -------------
__device__ __half g_xh[(size_t)N_TOK * D_DIM];
__device__ __half g_w1h[(size_t)N_EXP * 2 * H_DIM * D_DIM];  // row-interleaved up/gate
__device__ __half g_w2th[(size_t)N_EXP * D_DIM * H_DIM];     // transposed w_down
__device__ __half g_hh[(size_t)N_TOK * H_DIM];
// counters: [0,128) x regions, [128,384) w1 regions, [384,640) w2 regions,
//           [640,768) gemm1 (e,mt) tiles
__device__ unsigned g_cnt[768];

// ------------------------- PTX helpers (compute_103-legal only) ------------
__device__ __forceinline__ uint32_t smem_u32(const void* p) {
    uint32_t a;
    asm("{ .reg .u64 t; cvta.to.shared.u64 t, %1; cvt.u32.u64 %0, t; }"
        : "=r"(a) : "l"(p));
    return a;
}

__device__ __forceinline__ void cp16(uint32_t dst, const void* src) {
    asm volatile("cp.async.cg.shared.global [%0], [%1], 16;\n"
                 :: "r"(dst), "l"(src));
}
__device__ __forceinline__ void cp_commit() {
    asm volatile("cp.async.commit_group;\n" ::: "memory");
}
template <int NN>
__device__ __forceinline__ void cp_wait() {
    asm volatile("cp.async.wait_group %0;\n" :: "n"(NN) : "memory");
}

__device__ __forceinline__ void ldsm4(uint32_t* r, uint32_t addr) {
    asm volatile("ldmatrix.sync.aligned.m8n8.x4.shared.b16 {%0,%1,%2,%3}, [%4];"
                 : "=r"(r[0]), "=r"(r[1]), "=r"(r[2]), "=r"(r[3]) : "r"(addr));
}

__device__ __forceinline__ void mma16816(float* c, const uint32_t* a,
                                         uint32_t b0, uint32_t b1) {
    asm volatile(
        "mma.sync.aligned.m16n8k16.row.col.f32.f16.f16.f32 "
        "{%0,%1,%2,%3}, {%4,%5,%6,%7}, {%8,%9}, {%0,%1,%2,%3};"
        : "+f"(c[0]), "+f"(c[1]), "+f"(c[2]), "+f"(c[3])
        : "r"(a[0]), "r"(a[1]), "r"(a[2]), "r"(a[3]), "r"(b0), "r"(b1));
}

__device__ __forceinline__ unsigned ld_acq(const unsigned* p) {
    unsigned v;
    asm volatile("ld.acquire.gpu.u32 %0, [%1];" : "=r"(v) : "l"(p) : "memory");
    return v;
}

__device__ __forceinline__ void signal_done(unsigned* c) {
    __threadfence();
    __syncthreads();
    if (threadIdx.x == 0) atomicAdd(c, 1u);
}

__device__ __forceinline__ void wait2(const unsigned* c1, unsigned t1,
                                      const unsigned* c2, unsigned t2) {
    if (threadIdx.x == 0) {
        while (ld_acq(c1) < t1 || ld_acq(c2) < t2) __nanosleep(256);
    }
    __syncthreads();
}

// ------------------------- GEMM body (round-10 structure) ------------------
// C = A x B^T.  CTA tile 128(m) x 128(n), 256 threads (8 warps, 4m x 2n,
// warp tile 32x64). kchunk 64 (128B rows, SW128). 3-stage ring, 1
// barrier/chunk, 2 CTAs/SM.
#define OFF_B  16384
#define STAGE_BYTES 32768            // A(16K) + B(16K)
#define GEMM_SMEM (3 * STAGE_BYTES)  // 96KB -> 2 CTAs/SM

template <int K, bool FUSE_SILU>
__device__ __forceinline__ void gemm_body(
    const __half* __restrict__ A, const __half* __restrict__ B,
    float* __restrict__ C, __half* __restrict__ H, char* smem, int e, int mt,
    int nt) {
    uint32_t sbase = smem_u32(smem);
    int tid = threadIdx.x, wid = tid >> 5, lane = tid & 31;

    int lrow = tid >> 3, lc16 = tid & 7;  // lrow 0..31, lc16 0..7
    const char* gA = (const char*)(A + ((size_t)e * 1024 + mt * 128 + lrow) * K +
                                   lc16 * 8);
    const char* gB = (const char*)(B + ((size_t)e * 2048 + nt * 128 + lrow) * K +
                                   lc16 * 8);
    uint32_t soL = (uint32_t)(lrow * 128 + lc16 * 16);
    soL ^= (soL >> 3) & 0x70;

    float acc[2][8][4];
#pragma unroll
    for (int a = 0; a < 2; a++)
#pragma unroll
        for (int b = 0; b < 8; b++)
#pragma unroll
            for (int c = 0; c < 4; c++) acc[a][b][c] = 0.0f;

    int wm = wid & 3, wn = wid >> 2;  // 4m x 2n

#define LOAD_STAGE(SB, KC)                                                    \
    do {                                                                      \
        const char* a0 = gA + (size_t)(KC)*128;                               \
        const char* b0 = gB + (size_t)(KC)*128;                               \
        _Pragma("unroll") for (int j = 0; j < 4; j++)                         \
            cp16((SB) + soL + j * 4096, a0 + (size_t)j * 32 * (K * 2));       \
        _Pragma("unroll") for (int j = 0; j < 4; j++)                         \
            cp16((SB) + OFF_B + soL + j * 4096, b0 + (size_t)j * 32 * (K * 2));\
    } while (0)

    uint32_t sb[3] = {sbase, sbase + STAGE_BYTES, sbase + 2 * STAGE_BYTES};
    constexpr int kiters = K >> 6;
    LOAD_STAGE(sb[0], 0);
    cp_commit();
    LOAD_STAGE(sb[1], 1);
    cp_commit();

    // swizzled ldsm offsets; sw(base + kd) = sw(base) ^ kd for kd in bits 5-6
    uint32_t aOff[2], bOff[4];
    {
        uint32_t aBase =
            (uint32_t)((wm * 32 + (lane & 15)) * 128 + ((lane >> 4) & 1) * 16);
        uint32_t bBase =
            (uint32_t)((wn * 64 + (lane & 7) + ((lane >> 4) & 1) * 8) * 128 +
                       ((lane >> 3) & 1) * 16);
#pragma unroll
        for (int mf = 0; mf < 2; mf++) {
            uint32_t o = aBase + mf * 2048;
            aOff[mf] = o ^ ((o >> 3) & 0x70);
        }
#pragma unroll
        for (int np = 0; np < 4; np++) {
            uint32_t o = bBase + np * 2048;
            bOff[np] = (o ^ ((o >> 3) & 0x70)) + OFF_B;
        }
    }

#pragma unroll 1
    for (int kc = 0; kc < kiters; kc++) {
        uint32_t s = sb[kc % 3];
        cp_wait<1>();
        __syncthreads();

        uint32_t af[2][2][4], bf[2][4][4];
#pragma unroll
        for (int mf = 0; mf < 2; mf++) ldsm4(af[0][mf], s + aOff[mf]);
#pragma unroll
        for (int np = 0; np < 4; np++) ldsm4(bf[0][np], s + bOff[np]);

#pragma unroll
        for (int k16 = 0; k16 < 4; k16++) {
            int cur = k16 & 1, nxt = cur ^ 1;
            if (k16 < 3) {
                uint32_t kd = (uint32_t)(k16 + 1) * 32;
#pragma unroll
                for (int mf = 0; mf < 2; mf++)
                    ldsm4(af[nxt][mf], s + (aOff[mf] ^ kd));
#pragma unroll
                for (int np = 0; np < 4; np++)
                    ldsm4(bf[nxt][np], s + (bOff[np] ^ kd));
            }
#pragma unroll
            for (int mf = 0; mf < 2; mf++)
#pragma unroll
                for (int np = 0; np < 4; np++) {
                    mma16816(acc[mf][2 * np], af[cur][mf], bf[cur][np][0],
                             bf[cur][np][1]);
                    mma16816(acc[mf][2 * np + 1], af[cur][mf], bf[cur][np][2],
                             bf[cur][np][3]);
                }
        }
        if (kc + 2 < kiters) LOAD_STAGE(sb[(kc + 2) % 3], kc + 2);
        cp_commit();
    }

    // ---- epilogue ----
    int row0 = wm * 32 + (lane >> 2);
    if (FUSE_SILU) {
        size_t grow0 = (size_t)e * 1024 + mt * 128 + row0;
        int hcol = nt * 64 + wn * 32 + (lane & 3);
#pragma unroll
        for (int mf = 0; mf < 2; mf++)
#pragma unroll
            for (int nf = 0; nf < 8; nf++) {
                size_t r = grow0 + mf * 16;
                int hc = hcol + nf * 4;
                float u0 = acc[mf][nf][0], g0 = acc[mf][nf][1];
                float u1 = acc[mf][nf][2], g1 = acc[mf][nf][3];
                float h0 = u0 * g0 * (1.0f / (1.0f + __expf(-g0)));
                float h1 = u1 * g1 * (1.0f / (1.0f + __expf(-g1)));
                H[r * H_DIM + hc] = __float2half(h0);
                H[(r + 8) * H_DIM + hc] = __float2half(h1);
            }
    } else {
        float* pC = C + ((size_t)e * 1024 + mt * 128) * 2048 + nt * 128;
        int col0 = wn * 64 + (lane & 3) * 2;
#pragma unroll
        for (int mf = 0; mf < 2; mf++)
#pragma unroll
            for (int nf = 0; nf < 8; nf++) {
                int r = row0 + mf * 16, c = col0 + nf * 8;
                float2 v0 = {acc[mf][nf][0], acc[mf][nf][1]};
                float2 v1 = {acc[mf][nf][2], acc[mf][nf][3]};
                *reinterpret_cast<float2*>(pC + (size_t)r * 2048 + c) = v0;
                *reinterpret_cast<float2*>(pC + (size_t)(r + 8) * 2048 + c) = v1;
            }
    }
#undef LOAD_STAGE
}

// ------------------------- mega-fused kernel -------------------------------
// bid layout (dispatch order = dependency order; waiters only wait on
// strictly lower bids -> deadlock-free given in-order CTA dispatch):
//   [0,    512): x convert.   region (e,mt): 128 rows x 2048 f32. 4 CTAs ea.
//   [512, 1536): w1 convert+interleave. region (e,nt): 128 dst rows. 4 CTAs.
//   [1536,2048): w2 transpose. region (e,nt): 128 d-rows x 1024 h. 2 CTAs.
//   [2048,4096): gemm1 tile (e,mt,nt): waits x(e,mt)==4 && w1(e,nt)==4.
//   [4096,6144): gemm2 tile (e,mt,nt): waits g1(e,mt)==16 && w2(e,nt)==2.
__global__ void __launch_bounds__(256, 2) mega_kernel(
    const float* __restrict__ x, const float* __restrict__ w1,
    const float* __restrict__ w2, float* __restrict__ out) {
    extern __shared__ char smem[];
    int bid = blockIdx.x;
    int tid = threadIdx.x;

    if (bid < 512) {
        // ---- x conversion: region = (e,mt) x-tile, 4 sub-CTAs ----
        int region = bid >> 2, sub = bid & 3;  // region: e*8+mt
        size_t base4 = (size_t)region * 65536 + sub * 16384;  // float4 units
        const float4* src = reinterpret_cast<const float4*>(x) + base4;
        uint2* dst = reinterpret_cast<uint2*>(g_xh) + base4;
#pragma unroll 4
        for (int k = 0; k < 64; k++) {
            float4 v = src[tid + k * 256];
            __half hv[4] = {__float2half(v.x), __float2half(v.y),
                            __float2half(v.z), __float2half(v.w)};
            dst[tid + k * 256] = *reinterpret_cast<uint2*>(hv);
        }
        signal_done(&g_cnt[region]);
    } else if (bid < 1536) {
        // ---- w1 convert + row-interleave: region = (e,nt) B-tile ----
        int rb = bid - 512;
        int region = rb >> 2, sub = rb & 3;  // region: e*16+nt
        int e = region >> 4, nt = region & 15;
#pragma unroll 1
        for (int k = 0; k < 64; k++) {
            int f = sub * 16384 + tid + k * 256;  // float4 idx in region
            int rr = f >> 9;                      // 512 float4 per row
            int c4 = (f & 511) << 2;
            int nr = nt * 128 + rr;               // interleaved dst row
            int j = nr >> 1;
            int srow = (nr & 1) ? (1024 + j) : j;
            float4 v = *reinterpret_cast<const float4*>(
                w1 + ((size_t)e * 2048 + srow) * D_DIM + c4);
            __half hv[4] = {__float2half(v.x), __float2half(v.y),
                            __float2half(v.z), __float2half(v.w)};
            *reinterpret_cast<uint2*>(
                g_w1h + ((size_t)e * 2048 + nr) * D_DIM + c4) =
                *reinterpret_cast<uint2*>(hv);
        }
        signal_done(&g_cnt[128 + region]);
    } else if (bid < 2048) {
        // ---- w2 transpose: region = (e,nt) gemm2 B-tile; sub splits h ----
        int rb = bid - 1536;
        int region = rb >> 1, sub = rb & 1;  // region: e*16+nt
        int e = region >> 4, nt = region & 15;
        float* tile = reinterpret_cast<float*>(smem);  // 32 x 33
        int tx = tid & 31, ty = tid >> 5;  // 32 x 8
#pragma unroll 1
        for (int t = 0; t < 64; t++) {       // 4 d-blocks x 16 h-blocks
            int dblk = t >> 4, hblk = t & 15;
            int d0 = nt * 128 + dblk * 32;
            int h0 = sub * 512 + hblk * 32;
            __syncthreads();
#pragma unroll
            for (int jj = 0; jj < 32; jj += 8)
                tile[(ty + jj) * 33 + tx] =
                    w2[((size_t)e * H_DIM + h0 + ty + jj) * D_DIM + d0 + tx];
            __syncthreads();
#pragma unroll
            for (int jj = 0; jj < 32; jj += 8)
                g_w2th[((size_t)e * D_DIM + d0 + ty + jj) * H_DIM + h0 + tx] =
                    __float2half(tile[tx * 33 + ty + jj]);
        }
        signal_done(&g_cnt[384 + region]);
    } else if (bid < 4096) {
        // ---- gemm1 ----
        int b = bid - 2048;
        int e = b >> 7, rr = b & 127, mt = rr >> 4, nt = rr & 15;
        wait2(&g_cnt[e * 8 + mt], 4u, &g_cnt[128 + e * 16 + nt], 4u);
        gemm_body<D_DIM, true>(g_xh, g_w1h, nullptr, g_hh, smem, e, mt, nt);
        signal_done(&g_cnt[640 + e * 8 + mt]);
    } else {
        // ---- gemm2 ----
        int b = bid - 4096;
        int e = b >> 7, rr = b & 127, mt = rr >> 4, nt = rr & 15;
        wait2(&g_cnt[640 + e * 8 + mt], 16u, &g_cnt[384 + e * 16 + nt], 2u);
        gemm_body<H_DIM, false>(g_hh, g_w2th, out, nullptr, smem, e, mt, nt);
    }
}

// ------------------------- launch ------------------------------------------
extern "C" void kernel_launch(void* const* d_in, const int* in_sizes, int n_in,
                              void* d_out, int out_size) {
    (void)in_sizes; (void)n_in; (void)out_size;
    const float* x = (const float*)d_in[0];
    const float* w1 = (const float*)d_in[1];
    const float* w2 = (const float*)d_in[2];
    float* out = (float*)d_out;

    cudaFuncSetAttribute(mega_kernel,
                         cudaFuncAttributeMaxDynamicSharedMemorySize, GEMM_SMEM);

    unsigned* cnt;
    cudaGetSymbolAddress((void**)&cnt, g_cnt);
    cudaMemsetAsync(cnt, 0, 768 * sizeof(unsigned));

    mega_kernel<<<6144, 256, GEMM_SMEM>>>(x, w1, w2, out);
}

// round 16
// speedup vs baseline: 1.1088x; 1.1088x over previous
#include <cuda_runtime.h>
#include <cuda_fp16.h>
#include <stdint.h>

#define N_TOK 16384
#define D_DIM 2048
#define H_DIM 1024
#define N_EXP 16

// ------------------------- scratch (device globals; no allocs) -------------
__device__ __half g_xh[(size_t)N_TOK * D_DIM];
__device__ __half g_w1h[(size_t)N_EXP * 2 * H_DIM * D_DIM];  // row-interleaved up/gate
__device__ __half g_w2th[(size_t)N_EXP * D_DIM * H_DIM];     // transposed w_down
__device__ __half g_hh[(size_t)N_TOK * H_DIM];
// counters: [0,128) x (e,mt) tgt32 | [128,384) w1 (e,nt) tgt32 |
//           [384,640) w2 (e,nt) tgt8 | [640,768) gemm1 (e,mt) tgt16
__device__ unsigned g_cnt[768];

// ------------------------- PTX helpers (compute_103-legal only) ------------
__device__ __forceinline__ uint32_t smem_u32(const void* p) {
    uint32_t a;
    asm("{ .reg .u64 t; cvta.to.shared.u64 t, %1; cvt.u32.u64 %0, t; }"
        : "=r"(a) : "l"(p));
    return a;
}

__device__ __forceinline__ void cp16(uint32_t dst, const void* src) {
    asm volatile("cp.async.cg.shared.global [%0], [%1], 16;\n"
                 :: "r"(dst), "l"(src));
}
__device__ __forceinline__ void cp_commit() {
    asm volatile("cp.async.commit_group;\n" ::: "memory");
}
template <int NN>
__device__ __forceinline__ void cp_wait() {
    asm volatile("cp.async.wait_group %0;\n" :: "n"(NN) : "memory");
}

__device__ __forceinline__ void ldsm4(uint32_t* r, uint32_t addr) {
    asm volatile("ldmatrix.sync.aligned.m8n8.x4.shared.b16 {%0,%1,%2,%3}, [%4];"
                 : "=r"(r[0]), "=r"(r[1]), "=r"(r[2]), "=r"(r[3]) : "r"(addr));
}

__device__ __forceinline__ void mma16816(float* c, const uint32_t* a,
                                         uint32_t b0, uint32_t b1) {
    asm volatile(
        "mma.sync.aligned.m16n8k16.row.col.f32.f16.f16.f32 "
        "{%0,%1,%2,%3}, {%4,%5,%6,%7}, {%8,%9}, {%0,%1,%2,%3};"
        : "+f"(c[0]), "+f"(c[1]), "+f"(c[2]), "+f"(c[3])
        : "r"(a[0]), "r"(a[1]), "r"(a[2]), "r"(a[3]), "r"(b0), "r"(b1));
}

__device__ __forceinline__ unsigned ld_acq(const unsigned* p) {
    unsigned v;
    asm volatile("ld.acquire.gpu.u32 %0, [%1];" : "=r"(v) : "l"(p) : "memory");
    return v;
}

__device__ __forceinline__ void signal_done(unsigned* c) {
    __threadfence();
    __syncthreads();
    if (threadIdx.x == 0) atomicAdd(c, 1u);
}

__device__ __forceinline__ void wait2(const unsigned* c1, unsigned t1,
                                      const unsigned* c2, unsigned t2) {
    if (threadIdx.x == 0) {
        while (ld_acq(c1) < t1 || ld_acq(c2) < t2) __nanosleep(256);
    }
    __syncthreads();
}

// ------------------------- GEMM body (round-10 structure) ------------------
#define OFF_B  16384
#define STAGE_BYTES 32768            // A(16K) + B(16K)
#define GEMM_SMEM (3 * STAGE_BYTES)  // 96KB -> 2 CTAs/SM

template <int K, bool FUSE_SILU>
__device__ __forceinline__ void gemm_body(
    const __half* __restrict__ A, const __half* __restrict__ B,
    float* __restrict__ C, __half* __restrict__ H, char* smem, int e, int mt,
    int nt) {
    uint32_t sbase = smem_u32(smem);
    int tid = threadIdx.x, wid = tid >> 5, lane = tid & 31;

    int lrow = tid >> 3, lc16 = tid & 7;
    const char* gA = (const char*)(A + ((size_t)e * 1024 + mt * 128 + lrow) * K +
                                   lc16 * 8);
    const char* gB = (const char*)(B + ((size_t)e * 2048 + nt * 128 + lrow) * K +
                                   lc16 * 8);
    uint32_t soL = (uint32_t)(lrow * 128 + lc16 * 16);
    soL ^= (soL >> 3) & 0x70;

    float acc[2][8][4];
#pragma unroll
    for (int a = 0; a < 2; a++)
#pragma unroll
        for (int b = 0; b < 8; b++)
#pragma unroll
            for (int c = 0; c < 4; c++) acc[a][b][c] = 0.0f;

    int wm = wid & 3, wn = wid >> 2;

#define LOAD_STAGE(SB, KC)                                                    \
    do {                                                                      \
        const char* a0 = gA + (size_t)(KC)*128;                               \
        const char* b0 = gB + (size_t)(KC)*128;                               \
        _Pragma("unroll") for (int j = 0; j < 4; j++)                         \
            cp16((SB) + soL + j * 4096, a0 + (size_t)j * 32 * (K * 2));       \
        _Pragma("unroll") for (int j = 0; j < 4; j++)                         \
            cp16((SB) + OFF_B + soL + j * 4096, b0 + (size_t)j * 32 * (K * 2));\
    } while (0)

    uint32_t sb[3] = {sbase, sbase + STAGE_BYTES, sbase + 2 * STAGE_BYTES};
    constexpr int kiters = K >> 6;
    LOAD_STAGE(sb[0], 0);
    cp_commit();
    LOAD_STAGE(sb[1], 1);
    cp_commit();

    uint32_t aOff[2], bOff[4];
    {
        uint32_t aBase =
            (uint32_t)((wm * 32 + (lane & 15)) * 128 + ((lane >> 4) & 1) * 16);
        uint32_t bBase =
            (uint32_t)((wn * 64 + (lane & 7) + ((lane >> 4) & 1) * 8) * 128 +
                       ((lane >> 3) & 1) * 16);
#pragma unroll
        for (int mf = 0; mf < 2; mf++) {
            uint32_t o = aBase + mf * 2048;
            aOff[mf] = o ^ ((o >> 3) & 0x70);
        }
#pragma unroll
        for (int np = 0; np < 4; np++) {
            uint32_t o = bBase + np * 2048;
            bOff[np] = (o ^ ((o >> 3) & 0x70)) + OFF_B;
        }
    }

#pragma unroll 1
    for (int kc = 0; kc < kiters; kc++) {
        uint32_t s = sb[kc % 3];
        cp_wait<1>();
        __syncthreads();

        uint32_t af[2][2][4], bf[2][4][4];
#pragma unroll
        for (int mf = 0; mf < 2; mf++) ldsm4(af[0][mf], s + aOff[mf]);
#pragma unroll
        for (int np = 0; np < 4; np++) ldsm4(bf[0][np], s + bOff[np]);

#pragma unroll
        for (int k16 = 0; k16 < 4; k16++) {
            int cur = k16 & 1, nxt = cur ^ 1;
            if (k16 < 3) {
                uint32_t kd = (uint32_t)(k16 + 1) * 32;
#pragma unroll
                for (int mf = 0; mf < 2; mf++)
                    ldsm4(af[nxt][mf], s + (aOff[mf] ^ kd));
#pragma unroll
                for (int np = 0; np < 4; np++)
                    ldsm4(bf[nxt][np], s + (bOff[np] ^ kd));
            }
#pragma unroll
            for (int mf = 0; mf < 2; mf++)
#pragma unroll
                for (int np = 0; np < 4; np++) {
                    mma16816(acc[mf][2 * np], af[cur][mf], bf[cur][np][0],
                             bf[cur][np][1]);
                    mma16816(acc[mf][2 * np + 1], af[cur][mf], bf[cur][np][2],
                             bf[cur][np][3]);
                }
        }
        if (kc + 2 < kiters) LOAD_STAGE(sb[(kc + 2) % 3], kc + 2);
        cp_commit();
    }

    int row0 = wm * 32 + (lane >> 2);
    if (FUSE_SILU) {
        size_t grow0 = (size_t)e * 1024 + mt * 128 + row0;
        int hcol = nt * 64 + wn * 32 + (lane & 3);
#pragma unroll
        for (int mf = 0; mf < 2; mf++)
#pragma unroll
            for (int nf = 0; nf < 8; nf++) {
                size_t r = grow0 + mf * 16;
                int hc = hcol + nf * 4;
                float u0 = acc[mf][nf][0], g0 = acc[mf][nf][1];
                float u1 = acc[mf][nf][2], g1 = acc[mf][nf][3];
                float h0 = u0 * g0 * (1.0f / (1.0f + __expf(-g0)));
                float h1 = u1 * g1 * (1.0f / (1.0f + __expf(-g1)));
                H[r * H_DIM + hc] = __float2half(h0);
                H[(r + 8) * H_DIM + hc] = __float2half(h1);
            }
    } else {
        float* pC = C + ((size_t)e * 1024 + mt * 128) * 2048 + nt * 128;
        int col0 = wn * 64 + (lane & 3) * 2;
#pragma unroll
        for (int mf = 0; mf < 2; mf++)
#pragma unroll
            for (int nf = 0; nf < 8; nf++) {
                int r = row0 + mf * 16, c = col0 + nf * 8;
                float2 v0 = {acc[mf][nf][0], acc[mf][nf][1]};
                float2 v1 = {acc[mf][nf][2], acc[mf][nf][3]};
                *reinterpret_cast<float2*>(pC + (size_t)r * 2048 + c) = v0;
                *reinterpret_cast<float2*>(pC + (size_t)(r + 8) * 2048 + c) = v1;
            }
    }
#undef LOAD_STAGE
}

// ------------------------- prepass bodies (high-MLP) -----------------------
// x convert: CTA = 4 rows (2048 float4) of expert e; sub in [0,256)
__device__ __forceinline__ void x_body(const float* __restrict__ x, int e,
                                       int sub, int tid) {
    size_t base4 = (size_t)e * 524288 + (size_t)sub * 2048;
    const float4* src = reinterpret_cast<const float4*>(x) + base4;
    uint2* dst = reinterpret_cast<uint2*>(g_xh) + base4;
#pragma unroll
    for (int k = 0; k < 8; k++) {
        float4 v = src[tid + k * 256];
        __half hv[4] = {__float2half(v.x), __float2half(v.y),
                        __float2half(v.z), __float2half(v.w)};
        dst[tid + k * 256] = *reinterpret_cast<uint2*>(hv);
    }
    signal_done(&g_cnt[e * 8 + (sub >> 5)]);
}

// w1 convert + interleave: CTA = 4 dst rows; sub in [0,512)
__device__ __forceinline__ void w1_body(const float* __restrict__ w1, int e,
                                        int sub, int tid) {
#pragma unroll
    for (int k = 0; k < 8; k++) {
        int ridx = sub * 2048 + tid + k * 256;  // float4 idx in expert dst
        int rr = ridx >> 9;                     // dst row (interleaved)
        int c4q = ridx & 511;
        int srow = (rr & 1) ? (1024 + (rr >> 1)) : (rr >> 1);
        float4 v = reinterpret_cast<const float4*>(
            w1)[((size_t)e * 2048 + srow) * 512 + c4q];
        __half hv[4] = {__float2half(v.x), __float2half(v.y),
                        __float2half(v.z), __float2half(v.w)};
        reinterpret_cast<uint2*>(
            g_w1h)[((size_t)e * 2048 + rr) * 512 + c4q] =
            *reinterpret_cast<uint2*>(hv);
    }
    signal_done(&g_cnt[128 + e * 16 + (sub >> 5)]);
}

// w2 transpose: CTA = 16 tiles (32x32) of region (e,nt); sub in [0,128)
__device__ __forceinline__ void w2_body(const float* __restrict__ w2, int e,
                                        int sub, int tid, char* smem) {
    int nt = sub >> 3, part = sub & 7;
    float* tile = reinterpret_cast<float*>(smem);  // 32 x 33
    int tx = tid & 31, ty = tid >> 5;
#pragma unroll 1
    for (int tt = 0; tt < 16; tt++) {
        int t = part * 16 + tt;
        int d0 = nt * 128 + (t >> 5) * 32;
        int h0 = (t & 31) * 32;
        __syncthreads();
#pragma unroll
        for (int jj = 0; jj < 32; jj += 8)
            tile[(ty + jj) * 33 + tx] =
                w2[((size_t)e * H_DIM + h0 + ty + jj) * D_DIM + d0 + tx];
        __syncthreads();
#pragma unroll
        for (int jj = 0; jj < 32; jj += 8)
            g_w2th[((size_t)e * D_DIM + d0 + ty + jj) * H_DIM + h0 + tx] =
                __float2half(tile[tx * 33 + ty + jj]);
    }
    signal_done(&g_cnt[384 + e * 16 + nt]);
}

// ------------------------- pipelined mega kernel ---------------------------
// Per-expert pipeline blocks (bids increase with stage):
//   block 0              : prepass(0) [896] + gemm1(0) [128]            =1024
//   block s (s=1..15)    : prepass(s) [896] + gemm1(s) [128]
//                          + gemm2(s-1) [128]                           =1152
//   tail                 : gemm2(15) [128]
// Waiters depend only on strictly-lower bids -> deadlock-free under
// in-order CTA dispatch (validated round 14). Steady state: gemm1(e) +
// gemm2(e-1) compute (256 CTAs) while prepass(e+1) streams DRAM.
__global__ void __launch_bounds__(256, 2) mega_kernel(
    const float* __restrict__ x, const float* __restrict__ w1,
    const float* __restrict__ w2, float* __restrict__ out) {
    extern __shared__ char smem[];
    int bid = blockIdx.x;
    int tid = threadIdx.x;

    int e, idx;          // expert for prepass/gemm1; idx within block
    int g2e = -1;        // expert for gemm2 work in this block (or -1)
    if (bid < 1024) {
        e = 0; idx = bid;
    } else if (bid < 18304) {
        int b = bid - 1024;
        int s = b / 1152;
        idx = b - s * 1152;
        e = s + 1;
        g2e = s;
    } else {
        e = -1; idx = 1024 + (bid - 18304);  // tail: gemm2(15)
        g2e = 15;
    }

    if (idx < 896) {
        // ---- prepass(e) ----
        if (idx < 256) x_body(x, e, idx, tid);
        else if (idx < 768) w1_body(w1, e, idx - 256, tid);
        else w2_body(w2, e, idx - 768, tid, smem);
    } else if (idx < 1024) {
        // ---- gemm1(e) tile ----
        int rr = idx - 896;
        int mt = rr >> 4, nt = rr & 15;
        wait2(&g_cnt[e * 8 + mt], 32u, &g_cnt[128 + e * 16 + nt], 32u);
        gemm_body<D_DIM, true>(g_xh, g_w1h, nullptr, g_hh, smem, e, mt, nt);
        signal_done(&g_cnt[640 + e * 8 + mt]);
    } else {
        // ---- gemm2(g2e) tile ----
        int rr = idx - 1024;
        int mt = rr >> 4, nt = rr & 15;
        wait2(&g_cnt[640 + g2e * 8 + mt], 16u, &g_cnt[384 + g2e * 16 + nt], 8u);
        gemm_body<H_DIM, false>(g_hh, g_w2th, out, nullptr, smem, g2e, mt, nt);
    }
}

// ------------------------- launch ------------------------------------------
extern "C" void kernel_launch(void* const* d_in, const int* in_sizes, int n_in,
                              void* d_out, int out_size) {
    (void)in_sizes; (void)n_in; (void)out_size;
    const float* x = (const float*)d_in[0];
    const float* w1 = (const float*)d_in[1];
    const float* w2 = (const float*)d_in[2];
    float* out = (float*)d_out;

    cudaFuncSetAttribute(mega_kernel,
                         cudaFuncAttributeMaxDynamicSharedMemorySize, GEMM_SMEM);

    unsigned* cnt;
    cudaGetSymbolAddress((void**)&cnt, g_cnt);
    cudaMemsetAsync(cnt, 0, 768 * sizeof(unsigned));

    mega_kernel<<<18432, 256, GEMM_SMEM>>>(x, w1, w2, out);
}